// round 11
// baseline (speedup 1.0000x reference)
#include <cuda_runtime.h>
#include <cstdint>

// ================= problem constants =================
#define BB 16
#define CC 256
#define NT 288                       // 9 warps
#define IB 3                         // i-rows per CTA
#define NIB 8                        // 24 / IB
#define YB (IB + 8)                  // 11 y-band rows
#define SROW 36                      // smem row stride (floats): (4g+t4)%32 bijective
#define X2SBUF (YB*32*SROW)          // 12672 floats per stage
#define X1SBUF (IB*24*SROW)          // 2592 floats per stage
#define X1OFF  (2*X2SBUF)            // 25344
#define SMEM_FLOATS (2*X2SBUF + 2*X1SBUF)   // 30528
#define SMEM_BYTES  (SMEM_FLOATS*4)         // 122112

// K-major, tf32-rounded: g_At[b][i*24+j][c], g_Bt[b][y*24+x][c]
__device__ __align__(16) float g_At[(size_t)BB * 576 * CC];
__device__ __align__(16) float g_Bt[(size_t)BB * 576 * CC];

__device__ __forceinline__ uint32_t smem_u32(const void* p) {
    uint32_t a;
    asm("{ .reg .u64 t; cvta.to.shared.u64 t, %1; cvt.u32.u64 %0, t; }"
        : "=r"(a) : "l"(p));
    return a;
}
__device__ __forceinline__ float tf32r(float x) {
    uint32_t u;
    asm("cvt.rna.tf32.f32 %0, %1;" : "=r"(u) : "f"(x));
    return __uint_as_float(u);
}
__device__ __forceinline__ void cp16(uint32_t s, const float* g) {
    asm volatile("cp.async.cg.shared.global [%0], [%1], 16;" :: "r"(s), "l"(g));
}
__device__ __forceinline__ void mma_tf32(float* d, const uint32_t* a,
                                         const uint32_t* b) {
    asm volatile(
        "mma.sync.aligned.m16n8k8.row.col.f32.tf32.tf32.f32 "
        "{%0,%1,%2,%3}, {%4,%5,%6,%7}, {%8,%9}, {%0,%1,%2,%3};"
        : "+f"(d[0]), "+f"(d[1]), "+f"(d[2]), "+f"(d[3])
        : "r"(a[0]), "r"(a[1]), "r"(a[2]), "r"(a[3]), "r"(b[0]), "r"(b[1]));
}

// ===== prep: even-grid compact + transpose to K-major + tf32 round =====
__global__ void prep_kernel(const float* __restrict__ x1,
                            const float* __restrict__ x2)
{
    __shared__ float tile[32][25];
    const int cb  = blockIdx.x;          // 0..7
    const int row = blockIdx.y;          // 0..23
    const int b   = blockIdx.z >> 1;
    const bool isB = blockIdx.z & 1;
    const float* src = isB ? x2 : x1;
    float* dst = isB ? g_Bt : g_At;
    const int c0 = cb * 32;
    const int t  = threadIdx.x;
    {
        const int c  = t >> 3;
        const int j0 = (t & 7) * 3;
        const float* srow = src + ((size_t)(b * CC + c0 + c) * 48 + 2 * row) * 48;
        #pragma unroll
        for (int e = 0; e < 3; ++e)
            tile[c][j0 + e] = tf32r(srow[2 * (j0 + e)]);
    }
    __syncthreads();
    const int c = t & 31, jb = t >> 5;
    #pragma unroll
    for (int e = 0; e < 3; ++e) {
        int j = jb + 8 * e;
        dst[((size_t)(b * 576 + row * 24 + j)) * CC + c0 + c] = tile[c][j];
    }
}

// ===== banded TF32 warp-MMA =====
__global__ __launch_bounds__(NT, 1)
void mma_kernel(float* __restrict__ out)
{
    extern __shared__ float sm[];
    const uint32_t smb = smem_u32(sm);
    const int tid = threadIdx.x;
    const int q = tid >> 5, lane = tid & 31;
    const int g = lane >> 2, t4 = lane & 3;
    const int ibp = blockIdx.x;          // 0..7
    const int b   = blockIdx.y;
    const int i0  = ibp * IB;

    // loader roles (fixed per thread, zero math in loop)
    const float* gbase = nullptr;
    uint32_t sbase = 0;
    bool lvalid = false;
    int nrep = 0, grep = 0, srep = 0;
    if (tid < YB * 24) {                 // x2: 264 threads, one (y,x) each
        int y = tid / 24, x = tid % 24;
        int yg = i0 - 4 + y;
        lvalid = ((unsigned)yg < 24u);
        if (lvalid) gbase = g_Bt + ((size_t)(b * 576 + yg * 24 + x)) * CC;
        sbase = smb + (uint32_t)((y * 32 + x + 4) * SROW) * 4u;
        nrep = 1;
    } else {                             // x1: 24 threads, 3 rows each (ii)
        int j = tid - YB * 24;
        lvalid = true;
        gbase = g_At + ((size_t)(b * 576 + i0 * 24 + j)) * CC;
        sbase = smb + (uint32_t)(X1OFF + j * SROW) * 4u;
        nrep = IB; grep = 24 * CC; srep = 24 * SROW * 4;
    }

    for (int idx = tid; idx < SMEM_FLOATS; idx += NT) sm[idx] = 0.f;
    __syncthreads();

    auto issue = [&](int k) {
        if (lvalid) {
            uint32_t so = (uint32_t)(k & 1) * ((tid < YB * 24 ? X2SBUF : X1SBUF) * 4u);
            const float* gk = gbase + k * 32;
            #pragma unroll
            for (int rep = 0; rep < IB; ++rep) {
                if (rep < nrep) {
                    #pragma unroll
                    for (int s = 0; s < 8; ++s)   // 8 x 16B = full 32-float row
                        cp16(sbase + so + (uint32_t)(rep * srep) + s * 16u,
                             gk + rep * grep + s * 4);
                }
            }
        }
        asm volatile("cp.async.commit_group;" ::: "memory");
    };

    issue(0);
    issue(1);

    float acc[IB][2][3][4];
    #pragma unroll
    for (int ii = 0; ii < IB; ++ii)
        #pragma unroll
        for (int mt = 0; mt < 2; ++mt)
            #pragma unroll
            for (int nt = 0; nt < 3; ++nt)
                #pragma unroll
                for (int e = 0; e < 4; ++e) acc[ii][mt][nt][e] = 0.f;

    #pragma unroll 1
    for (int k = 0; k < 8; ++k) {
        if (k < 7) asm volatile("cp.async.wait_group 1;" ::: "memory");
        else       asm volatile("cp.async.wait_group 0;" ::: "memory");
        __syncthreads();                 // chunk k resident

        const float* X2 = sm + (k & 1) * X2SBUF;
        const float* X1 = sm + X1OFF + (k & 1) * X1SBUF;
        #pragma unroll
        for (int kc = 0; kc < 4; ++kc) {
            const int kb = kc * 8 + t4;
            uint32_t af[IB][2][4], bf[IB][3][2];
            #pragma unroll
            for (int ii = 0; ii < IB; ++ii) {
                const float* arow = X2 + ((q + ii) * 32 + g) * SROW + kb;
                #pragma unroll
                for (int mt = 0; mt < 2; ++mt) {
                    const float* ap = arow + mt * 16 * SROW;
                    af[ii][mt][0] = __float_as_uint(ap[0]);
                    af[ii][mt][1] = __float_as_uint(ap[8 * SROW]);
                    af[ii][mt][2] = __float_as_uint(ap[4]);
                    af[ii][mt][3] = __float_as_uint(ap[8 * SROW + 4]);
                }
                const float* brow = X1 + (ii * 24 + g) * SROW + kb;
                #pragma unroll
                for (int nt = 0; nt < 3; ++nt) {
                    const float* bp = brow + nt * 8 * SROW;
                    bf[ii][nt][0] = __float_as_uint(bp[0]);
                    bf[ii][nt][1] = __float_as_uint(bp[4]);
                }
            }
            #pragma unroll
            for (int ii = 0; ii < IB; ++ii)
                #pragma unroll
                for (int mt = 0; mt < 2; ++mt)
                    #pragma unroll
                    for (int nt = 0; nt < 3; ++nt)
                        mma_tf32(acc[ii][mt][nt], af[ii][mt], bf[ii][nt]);
        }
        __syncthreads();                 // stage k&1 free
        if (k + 2 < 8) issue(k + 2);
    }
    __syncthreads();

    // epilogue: warp q scratch 32x25 in stage-0 region
    float* S = sm + q * 800;
    const float sc = 1.0f / 256.0f;
    #pragma unroll 1
    for (int ii = 0; ii < IB; ++ii) {
        #pragma unroll
        for (int mt = 0; mt < 2; ++mt)
            #pragma unroll
            for (int nt = 0; nt < 3; ++nt) {
                float* s0 = S + (mt * 16 + g) * 25 + nt * 8 + 2 * t4;
                s0[0]        = acc[ii][mt][nt][0];
                s0[1]        = acc[ii][mt][nt][1];
                s0[8 * 25]   = acc[ii][mt][nt][2];
                s0[8 * 25+1] = acc[ii][mt][nt][3];
            }
        __syncwarp();
        float* ob = out + ((size_t)b * 81 + q * 9) * 576 + (i0 + ii) * 24;
        if (lane < 24) {
            #pragma unroll
            for (int p = 0; p < 9; ++p)
                ob[p * 576 + lane] = S[(lane + p) * 25 + lane] * sc;
        }
        __syncwarp();
    }
}

extern "C" void kernel_launch(void* const* d_in, const int* in_sizes, int n_in,
                              void* d_out, int out_size)
{
    const float* x1 = (const float*)d_in[0];
    const float* x2 = (const float*)d_in[1];
    float* out = (float*)d_out;

    cudaFuncSetAttribute(mma_kernel,
                         cudaFuncAttributeMaxDynamicSharedMemorySize, SMEM_BYTES);

    dim3 pgrid(8, 24, 32);
    prep_kernel<<<pgrid, 256>>>(x1, x2);              // launch 0
    dim3 mgrid(NIB, BB);
    mma_kernel<<<mgrid, NT, SMEM_BYTES>>>(out);       // launch 1 -> idx 3 profiled
}

// round 12
// speedup vs baseline: 1.7155x; 1.7155x over previous
#include <cuda_runtime.h>
#include <cstdint>

// ================= problem constants =================
#define BB 16
#define CC 256
#define NT 288                       // 9 warps = 9 q-displacements
#define YB 9                         // y-band rows per CTA (i fixed)
#define SROW 36                      // smem row stride: bank (4g+t4)%32 bijective
#define X2SBUF (YB*32*SROW)          // 10368 floats per stage
#define X1SBUF (24*SROW)             // 864 floats per stage
#define X1OFF  (2*X2SBUF)            // 20736
#define SMEM_FLOATS (2*X2SBUF + 2*X1SBUF)   // 22464
#define SMEM_BYTES  (SMEM_FLOATS*4)         // 89856

// K-major, tf32-rounded: g_At[b][i*24+j][c], g_Bt[b][y*24+x][c]
__device__ __align__(16) float g_At[(size_t)BB * 576 * CC];
__device__ __align__(16) float g_Bt[(size_t)BB * 576 * CC];

__device__ __forceinline__ uint32_t smem_u32(const void* p) {
    uint32_t a;
    asm("{ .reg .u64 t; cvta.to.shared.u64 t, %1; cvt.u32.u64 %0, t; }"
        : "=r"(a) : "l"(p));
    return a;
}
__device__ __forceinline__ float tf32r(float x) {
    uint32_t u;
    asm("cvt.rna.tf32.f32 %0, %1;" : "=r"(u) : "f"(x));
    return __uint_as_float(u);
}
__device__ __forceinline__ void cp16(uint32_t s, const float* g) {
    asm volatile("cp.async.cg.shared.global [%0], [%1], 16;" :: "r"(s), "l"(g));
}
__device__ __forceinline__ void mma_tf32(float* d, const uint32_t* a,
                                         const uint32_t* b) {
    asm volatile(
        "mma.sync.aligned.m16n8k8.row.col.f32.tf32.tf32.f32 "
        "{%0,%1,%2,%3}, {%4,%5,%6,%7}, {%8,%9}, {%0,%1,%2,%3};"
        : "+f"(d[0]), "+f"(d[1]), "+f"(d[2]), "+f"(d[3])
        : "r"(a[0]), "r"(a[1]), "r"(a[2]), "r"(a[3]), "r"(b[0]), "r"(b[1]));
}

// ===== prep: even-grid compact + transpose to K-major + tf32 round =====
__global__ void prep_kernel(const float* __restrict__ x1,
                            const float* __restrict__ x2)
{
    __shared__ float tile[32][25];
    const int cb  = blockIdx.x;          // 0..7
    const int row = blockIdx.y;          // 0..23
    const int b   = blockIdx.z >> 1;
    const bool isB = blockIdx.z & 1;
    const float* src = isB ? x2 : x1;
    float* dst = isB ? g_Bt : g_At;
    const int c0 = cb * 32;
    const int t  = threadIdx.x;
    {
        const int c  = t >> 3;
        const int j0 = (t & 7) * 3;
        const float* srow = src + ((size_t)(b * CC + c0 + c) * 48 + 2 * row) * 48;
        #pragma unroll
        for (int e = 0; e < 3; ++e)
            tile[c][j0 + e] = tf32r(srow[2 * (j0 + e)]);
    }
    __syncthreads();
    const int c = t & 31, jb = t >> 5;
    #pragma unroll
    for (int e = 0; e < 3; ++e) {
        int j = jb + 8 * e;
        dst[((size_t)(b * 576 + row * 24 + j)) * CC + c0 + c] = tile[c][j];
    }
}

// ===== banded TF32 warp-MMA, one i-row per CTA =====
__global__ __launch_bounds__(NT, 2)
void mma_kernel(float* __restrict__ out)
{
    extern __shared__ float sm[];
    const uint32_t smb = smem_u32(sm);
    const int tid = threadIdx.x;
    const int q = tid >> 5, lane = tid & 31;
    const int g = lane >> 2, t4 = lane & 3;
    const int i0 = blockIdx.x;           // 0..23
    const int b  = blockIdx.y;

    // loader roles: x2 = 216 threads (one (y,x) row each), x1 = 24 threads
    const float* gbase = nullptr;
    uint32_t sbase = 0;
    bool lvalid = false;
    bool isx2 = (tid < YB * 24);
    if (isx2) {
        int y = tid / 24, x = tid % 24;
        int yg = i0 - 4 + y;
        lvalid = ((unsigned)yg < 24u);
        if (lvalid) gbase = g_Bt + ((size_t)(b * 576 + yg * 24 + x)) * CC;
        sbase = smb + (uint32_t)((y * 32 + x + 4) * SROW) * 4u;
    } else if (tid < YB * 24 + 24) {
        int j = tid - YB * 24;
        lvalid = true;
        gbase = g_At + ((size_t)(b * 576 + i0 * 24 + j)) * CC;
        sbase = smb + (uint32_t)(X1OFF + j * SROW) * 4u;
    }

    for (int idx = tid; idx < SMEM_FLOATS; idx += NT) sm[idx] = 0.f;
    __syncthreads();

    auto issue = [&](int k) {
        if (lvalid) {
            uint32_t so = (uint32_t)(k & 1) * ((isx2 ? X2SBUF : X1SBUF) * 4u);
            const float* gk = gbase + k * 32;
            #pragma unroll
            for (int s = 0; s < 8; ++s)      // 8 x 16B = full 32-float k-chunk
                cp16(sbase + so + s * 16u, gk + s * 4);
        }
        asm volatile("cp.async.commit_group;" ::: "memory");
    };

    issue(0);
    issue(1);

    float acc[2][3][4];
    #pragma unroll
    for (int mt = 0; mt < 2; ++mt)
        #pragma unroll
        for (int nt = 0; nt < 3; ++nt)
            #pragma unroll
            for (int e = 0; e < 4; ++e) acc[mt][nt][e] = 0.f;

    #pragma unroll 1
    for (int k = 0; k < 8; ++k) {
        if (k < 7) asm volatile("cp.async.wait_group 1;" ::: "memory");
        else       asm volatile("cp.async.wait_group 0;" ::: "memory");
        __syncthreads();                 // chunk k resident

        const float* X2 = sm + (k & 1) * X2SBUF;
        const float* X1 = sm + X1OFF + (k & 1) * X1SBUF;
        #pragma unroll
        for (int kc = 0; kc < 4; ++kc) {
            const int kb = kc * 8 + t4;
            uint32_t af[2][4], bf[3][2];
            const float* arow = X2 + (q * 32 + g) * SROW + kb;
            #pragma unroll
            for (int mt = 0; mt < 2; ++mt) {
                const float* ap = arow + mt * 16 * SROW;
                af[mt][0] = __float_as_uint(ap[0]);
                af[mt][1] = __float_as_uint(ap[8 * SROW]);
                af[mt][2] = __float_as_uint(ap[4]);
                af[mt][3] = __float_as_uint(ap[8 * SROW + 4]);
            }
            const float* brow = X1 + g * SROW + kb;
            #pragma unroll
            for (int nt = 0; nt < 3; ++nt) {
                const float* bp = brow + nt * 8 * SROW;
                bf[nt][0] = __float_as_uint(bp[0]);
                bf[nt][1] = __float_as_uint(bp[4]);
            }
            #pragma unroll
            for (int mt = 0; mt < 2; ++mt)
                #pragma unroll
                for (int nt = 0; nt < 3; ++nt)
                    mma_tf32(acc[mt][nt], af[mt], bf[nt]);
        }
        __syncthreads();                 // stage k&1 free
        if (k + 2 < 8) issue(k + 2);
    }
    __syncthreads();

    // epilogue: warp q scratch 32x25 in stage-0 region
    float* S = sm + q * 800;
    const float sc = 1.0f / 256.0f;
    #pragma unroll
    for (int mt = 0; mt < 2; ++mt)
        #pragma unroll
        for (int nt = 0; nt < 3; ++nt) {
            float* s0 = S + (mt * 16 + g) * 25 + nt * 8 + 2 * t4;
            s0[0]          = acc[mt][nt][0];
            s0[1]          = acc[mt][nt][1];
            s0[8 * 25]     = acc[mt][nt][2];
            s0[8 * 25 + 1] = acc[mt][nt][3];
        }
    __syncwarp();
    float* ob = out + ((size_t)b * 81 + q * 9) * 576 + i0 * 24;
    if (lane < 24) {
        #pragma unroll
        for (int p = 0; p < 9; ++p)
            ob[p * 576 + lane] = S[(lane + p) * 25 + lane] * sc;
    }
}

extern "C" void kernel_launch(void* const* d_in, const int* in_sizes, int n_in,
                              void* d_out, int out_size)
{
    const float* x1 = (const float*)d_in[0];
    const float* x2 = (const float*)d_in[1];
    float* out = (float*)d_out;

    cudaFuncSetAttribute(mma_kernel,
                         cudaFuncAttributeMaxDynamicSharedMemorySize, SMEM_BYTES);

    dim3 pgrid(8, 24, 32);
    prep_kernel<<<pgrid, 256>>>(x1, x2);              // launch 0
    dim3 mgrid(24, BB);
    mma_kernel<<<mgrid, NT, SMEM_BYTES>>>(out);       // launch 1 -> idx 3 profiled
}

// round 13
// speedup vs baseline: 1.8688x; 1.0894x over previous
#include <cuda_runtime.h>
#include <cstdint>

// ================= problem constants =================
#define BB 16
#define CC 256
#define NT 288                       // 9 warps = 9 q-displacements
#define SROW1 260                    // x1 smem row stride (floats): 260%32=4 -> conflict-free
#define X1ROWS 48                    // 2 i-rows x 24 j
#define SMEM_BYTES (X1ROWS*SROW1*4)  // 49920

// A: K-major [b][i*24+j][c]
__device__ __align__(16) float g_At[(size_t)BB * 576 * CC];
// B: padded [b][y'=y+4 (32)][k (256)][x'=x+4 (32)]; .bss zeros = band padding
__device__ __align__(16) float g_B2[(size_t)BB * 32 * CC * 32];

__device__ __forceinline__ float tf32r(float x) {
    uint32_t u;
    asm("cvt.rna.tf32.f32 %0, %1;" : "=r"(u) : "f"(x));
    return __uint_as_float(u);
}
__device__ __forceinline__ uint32_t smem_u32(const void* p) {
    uint32_t a;
    asm("{ .reg .u64 t; cvta.to.shared.u64 t, %1; cvt.u32.u64 %0, t; }"
        : "=r"(a) : "l"(p));
    return a;
}
__device__ __forceinline__ void cp16(uint32_t s, const float* g) {
    asm volatile("cp.async.cg.shared.global [%0], [%1], 16;" :: "r"(s), "l"(g));
}
__device__ __forceinline__ void mma_tf32(float* d, const uint32_t* a,
                                         const uint32_t* b) {
    asm volatile(
        "mma.sync.aligned.m16n8k8.row.col.f32.tf32.tf32.f32 "
        "{%0,%1,%2,%3}, {%4,%5,%6,%7}, {%8,%9}, {%0,%1,%2,%3};"
        : "+f"(d[0]), "+f"(d[1]), "+f"(d[2]), "+f"(d[3])
        : "r"(a[0]), "r"(a[1]), "r"(a[2]), "r"(a[3]), "r"(b[0]), "r"(b[1]));
}

// ===== prep: even-grid compact + tf32 round; A->K-major, B->padded [y'][k][x'] =====
__global__ void prep_kernel(const float* __restrict__ x1,
                            const float* __restrict__ x2)
{
    __shared__ float tile[32][25];
    const int cb  = blockIdx.x;          // 0..7 : 32-channel block
    const int row = blockIdx.y;          // 0..23 : i (A) or y (B)
    const int b   = blockIdx.z >> 1;
    const bool isB = blockIdx.z & 1;
    const float* src = isB ? x2 : x1;
    const int c0 = cb * 32;
    const int t  = threadIdx.x;
    {
        const int c  = t >> 3;
        const int j0 = (t & 7) * 3;
        const float* srow = src + ((size_t)(b * CC + c0 + c) * 48 + 2 * row) * 48;
        #pragma unroll
        for (int e = 0; e < 3; ++e)
            tile[c][j0 + e] = tf32r(srow[2 * (j0 + e)]);
    }
    __syncthreads();
    if (!isB) {
        const int c = t & 31, jb = t >> 5;
        #pragma unroll
        for (int e = 0; e < 3; ++e) {
            int j = jb + 8 * e;
            g_At[((size_t)(b * 576 + row * 24 + j)) * CC + c0 + c] = tile[c][j];
        }
    } else {
        if (t < 192) {                   // 32 c x 6 float4 per c
            int c = t / 6, s = t % 6;
            float4 v = make_float4(tile[c][4*s], tile[c][4*s+1],
                                   tile[c][4*s+2], tile[c][4*s+3]);
            *(float4*)(g_B2 + (((size_t)(b * 32 + row + 4) * CC + c0 + c) * 32
                               + 4 + 4 * s)) = v;
        }
    }
}

// ===== barrier-free banded TF32 warp-MMA; 2 i-rows per CTA =====
__global__ __launch_bounds__(NT, 2)
void mma_kernel(float* __restrict__ out)
{
    extern __shared__ float sm[];
    const uint32_t smb = smem_u32(sm);
    const int tid = threadIdx.x;
    const int q = tid >> 5, lane = tid & 31;
    const int g = lane >> 2, t4 = lane & 3;
    const int i0 = blockIdx.x * 2;       // 0,2,..,22
    const int b  = blockIdx.y;

    // ---- one-shot x1 tile load: 48 rows x 256 k, stride SROW1 ----
    {
        const float* Ab = g_At + (size_t)(b * 576 + i0 * 24) * CC;
        for (int e = tid; e < X1ROWS * 64; e += NT) {
            int r = e >> 6, s = e & 63;
            cp16(smb + (uint32_t)(r * (SROW1 * 4) + s * 16), Ab + r * CC + s * 4);
        }
        asm volatile("cp.async.commit_group;" ::: "memory");
        asm volatile("cp.async.wait_group 0;" ::: "memory");
    }
    __syncthreads();                     // the ONLY block barrier before epilogue

    // x2 fragment base: y' = i0 + q (+ii), lane offset t4*32 + g
    const float* __restrict__ Bb = g_B2
        + ((size_t)(b * 32 + i0 + q) * CC) * 32 + t4 * 32 + g;

    float acc[2][2][3][4];
    #pragma unroll
    for (int ii = 0; ii < 2; ++ii)
        #pragma unroll
        for (int mt = 0; mt < 2; ++mt)
            #pragma unroll
            for (int nt = 0; nt < 3; ++nt)
                #pragma unroll
                for (int e = 0; e < 4; ++e) acc[ii][mt][nt][e] = 0.f;

    #pragma unroll 2
    for (int kc = 0; kc < 32; ++kc) {
        const float* Bk = Bb + kc * (8 * 32);   // k += 8 per step
        uint32_t af[2][2][4], bf[2][3][2];
        #pragma unroll
        for (int ii = 0; ii < 2; ++ii) {
            #pragma unroll
            for (int mt = 0; mt < 2; ++mt) {
                const float* ap = Bk + ii * (CC * 32) + mt * 16;
                af[ii][mt][0] = __float_as_uint(ap[0]);     // k=t4,   x=g
                af[ii][mt][1] = __float_as_uint(ap[8]);     // k=t4,   x=g+8
                af[ii][mt][2] = __float_as_uint(ap[128]);   // k=t4+4, x=g
                af[ii][mt][3] = __float_as_uint(ap[136]);   // k=t4+4, x=g+8
            }
            #pragma unroll
            for (int nt = 0; nt < 3; ++nt) {
                const float* bp = sm + (ii * 24 + nt * 8 + g) * SROW1 + kc * 8 + t4;
                bf[ii][nt][0] = __float_as_uint(bp[0]);
                bf[ii][nt][1] = __float_as_uint(bp[4]);
            }
        }
        #pragma unroll
        for (int ii = 0; ii < 2; ++ii)
            #pragma unroll
            for (int mt = 0; mt < 2; ++mt)
                #pragma unroll
                for (int nt = 0; nt < 3; ++nt)
                    mma_tf32(acc[ii][mt][nt], af[ii][mt], bf[ii][nt]);
    }
    __syncthreads();                     // all warps done with x1s; reuse as scratch

    // epilogue: warp q scratch 32x25
    float* S = sm + q * 800;
    const float sc = 1.0f / 256.0f;
    #pragma unroll 1
    for (int ii = 0; ii < 2; ++ii) {
        #pragma unroll
        for (int mt = 0; mt < 2; ++mt)
            #pragma unroll
            for (int nt = 0; nt < 3; ++nt) {
                float* s0 = S + (mt * 16 + g) * 25 + nt * 8 + 2 * t4;
                s0[0]          = acc[ii][mt][nt][0];
                s0[1]          = acc[ii][mt][nt][1];
                s0[8 * 25]     = acc[ii][mt][nt][2];
                s0[8 * 25 + 1] = acc[ii][mt][nt][3];
            }
        __syncwarp();
        float* ob = out + ((size_t)b * 81 + q * 9) * 576 + (i0 + ii) * 24;
        if (lane < 24) {
            #pragma unroll
            for (int p = 0; p < 9; ++p)
                ob[p * 576 + lane] = S[(lane + p) * 25 + lane] * sc;
        }
        __syncwarp();
    }
}

extern "C" void kernel_launch(void* const* d_in, const int* in_sizes, int n_in,
                              void* d_out, int out_size)
{
    const float* x1 = (const float*)d_in[0];
    const float* x2 = (const float*)d_in[1];
    float* out = (float*)d_out;

    cudaFuncSetAttribute(mma_kernel,
                         cudaFuncAttributeMaxDynamicSharedMemorySize, SMEM_BYTES);

    dim3 pgrid(8, 24, 32);
    prep_kernel<<<pgrid, 256>>>(x1, x2);              // launch 0
    dim3 mgrid(12, BB);
    mma_kernel<<<mgrid, NT, SMEM_BYTES>>>(out);       // launch 1 -> idx 3 profiled
}

// round 14
// speedup vs baseline: 2.1669x; 1.1595x over previous
#include <cuda_runtime.h>
#include <cstdint>

// ================= problem constants =================
#define BB 16
#define CC 256
#define NT 288                       // 9 warps = 9 q-displacements
#define SROW1 264                    // x1 smem row stride (floats), ≡8 mod 32
#define X1ROWS 48                    // 2 i-rows x 24 j
#define SMEM_BYTES (X1ROWS*SROW1*4)  // 50688

// A: K-major, channel pair-permuted within 8: g_At[b][i*24+j][k']
__device__ __align__(16) float g_At[(size_t)BB * 576 * CC];
// B: [b][y'(32)][kc(32)][khalf(2)][x'(32)*4 + k4]; .bss zeros = band padding
__device__ __align__(16) float g_B2[(size_t)BB * 32 * 32 * 2 * 128];

__device__ __forceinline__ float tf32r(float x) {
    uint32_t u;
    asm("cvt.rna.tf32.f32 %0, %1;" : "=r"(u) : "f"(x));
    return __uint_as_float(u);
}
__device__ __forceinline__ uint32_t smem_u32(const void* p) {
    uint32_t a;
    asm("{ .reg .u64 t; cvta.to.shared.u64 t, %1; cvt.u32.u64 %0, t; }"
        : "=r"(a) : "l"(p));
    return a;
}
__device__ __forceinline__ void cp16(uint32_t s, const float* g) {
    asm volatile("cp.async.cg.shared.global [%0], [%1], 16;" :: "r"(s), "l"(g));
}
__device__ __forceinline__ void mma_tf32(float* d, const uint32_t* a,
                                         const uint32_t* b) {
    asm volatile(
        "mma.sync.aligned.m16n8k8.row.col.f32.tf32.tf32.f32 "
        "{%0,%1,%2,%3}, {%4,%5,%6,%7}, {%8,%9}, {%0,%1,%2,%3};"
        : "+f"(d[0]), "+f"(d[1]), "+f"(d[2]), "+f"(d[3])
        : "r"(a[0]), "r"(a[1]), "r"(a[2]), "r"(a[3]), "r"(b[0]), "r"(b[1]));
}

// ===== prep: even-grid compact + tf32; A->pair-permuted K-major, B->k4-interleaved =====
__global__ void prep_kernel(const float* __restrict__ x1,
                            const float* __restrict__ x2)
{
    __shared__ float tile[32][25];
    const int row = blockIdx.x;          // 0..23 : i (A) or y (B)
    const int b   = blockIdx.y >> 1;
    const bool isB = blockIdx.y & 1;
    const float* src = isB ? x2 : x1;
    const int t = threadIdx.x;

    #pragma unroll 1
    for (int cb = 0; cb < 8; ++cb) {
        const int c0 = cb * 32;
        {
            const int c  = t >> 3;
            const int j0 = (t & 7) * 3;
            const float* srow = src + ((size_t)(b * CC + c0 + c) * 48 + 2 * row) * 48;
            #pragma unroll
            for (int e = 0; e < 3; ++e)
                tile[c][j0 + e] = tf32r(srow[2 * (j0 + e)]);
        }
        __syncthreads();
        if (!isB) {
            const int c = t & 31, jb = t >> 5;
            const int c8 = c & 7;
            const int cp = (c & ~7) + ((c8 < 4) ? 2 * c8 : 2 * (c8 - 4) + 1);
            #pragma unroll
            for (int e = 0; e < 3; ++e) {
                int j = jb + 8 * e;
                g_At[((size_t)(b * 576 + row * 24 + j)) * CC + c0 + cp] = tile[c][j];
            }
        } else {
            #pragma unroll
            for (int e = 0; e < 3; ++e) {
                int lin = t + 256 * e;           // 0..767
                int region = lin / 96;           // 0..7
                int o96 = lin - region * 96;     // 0..95
                int kcl = region >> 1, kh = region & 1;
                int x = o96 >> 2, k4 = o96 & 3;
                float v = tile[kcl * 8 + kh * 4 + k4][x];
                size_t idx = ((((size_t)(b * 32 + row + 4) * 32 + cb * 4 + kcl) * 2 + kh)
                              * 128) + 16 + o96;
                g_B2[idx] = v;
            }
        }
        __syncthreads();
    }
}

// ===== barrier-free banded TF32 warp-MMA; 2 i-rows per CTA =====
__global__ __launch_bounds__(NT, 2)
void mma_kernel(float* __restrict__ out)
{
    extern __shared__ float sm[];
    const uint32_t smb = smem_u32(sm);
    const int tid = threadIdx.x;
    const int q = tid >> 5, lane = tid & 31;
    const int g = lane >> 2, t4 = lane & 3;
    const int i0 = blockIdx.x * 2;       // 0,2,..,22
    const int b  = blockIdx.y;

    // ---- one-shot x1 tile load: 48 rows x 256 k' (pair-permuted) ----
    {
        const float* Ab = g_At + (size_t)(b * 576 + i0 * 24) * CC;
        for (int e = tid; e < X1ROWS * 64; e += NT) {
            int r = e >> 6, s = e & 63;
            cp16(smb + (uint32_t)(r * (SROW1 * 4) + s * 16), Ab + r * CC + s * 4);
        }
        asm volatile("cp.async.commit_group;" ::: "memory");
        asm volatile("cp.async.wait_group 0;" ::: "memory");
    }
    __syncthreads();                     // the ONLY block barrier before epilogue

    // x2 fragment base: every af LDG.32 hits one 128B line (offset = lane)
    const float* __restrict__ Bq = g_B2
        + (size_t)(b * 32 + i0 + q) * 8192 + lane;

    float acc[2][2][3][4];
    #pragma unroll
    for (int ii = 0; ii < 2; ++ii)
        #pragma unroll
        for (int mt = 0; mt < 2; ++mt)
            #pragma unroll
            for (int nt = 0; nt < 3; ++nt)
                #pragma unroll
                for (int e = 0; e < 4; ++e) acc[ii][mt][nt][e] = 0.f;

    #pragma unroll 2
    for (int kc = 0; kc < 32; ++kc) {
        uint32_t af[2][2][4], bf[2][3][2];
        #pragma unroll
        for (int ii = 0; ii < 2; ++ii) {
            const float* Bk = Bq + ii * 8192 + kc * 256;
            #pragma unroll
            for (int mt = 0; mt < 2; ++mt) {
                const float* ap = Bk + mt * 64;
                af[ii][mt][0] = __float_as_uint(ap[0]);     // kh0, x'=g(+16mt)
                af[ii][mt][1] = __float_as_uint(ap[32]);    // kh0, x'+8
                af[ii][mt][2] = __float_as_uint(ap[128]);   // kh1, x'
                af[ii][mt][3] = __float_as_uint(ap[160]);   // kh1, x'+8
            }
            #pragma unroll
            for (int nt = 0; nt < 3; ++nt) {
                float2 bp = *(const float2*)(sm + (ii * 24 + nt * 8 + g) * SROW1
                                             + kc * 8 + 2 * t4);
                bf[ii][nt][0] = __float_as_uint(bp.x);      // k = kc*8+t4
                bf[ii][nt][1] = __float_as_uint(bp.y);      // k = kc*8+t4+4
            }
        }
        #pragma unroll
        for (int ii = 0; ii < 2; ++ii)
            #pragma unroll
            for (int mt = 0; mt < 2; ++mt)
                #pragma unroll
                for (int nt = 0; nt < 3; ++nt)
                    mma_tf32(acc[ii][mt][nt], af[ii][mt], bf[ii][nt]);
    }
    __syncthreads();                     // warps done with x1s; reuse as scratch

    // epilogue: warp q scratch 32x25
    float* S = sm + q * 800;
    const float sc = 1.0f / 256.0f;
    #pragma unroll 1
    for (int ii = 0; ii < 2; ++ii) {
        #pragma unroll
        for (int mt = 0; mt < 2; ++mt)
            #pragma unroll
            for (int nt = 0; nt < 3; ++nt) {
                float* s0 = S + (mt * 16 + g) * 25 + nt * 8 + 2 * t4;
                s0[0]          = acc[ii][mt][nt][0];
                s0[1]          = acc[ii][mt][nt][1];
                s0[8 * 25]     = acc[ii][mt][nt][2];
                s0[8 * 25 + 1] = acc[ii][mt][nt][3];
            }
        __syncwarp();
        float* ob = out + ((size_t)b * 81 + q * 9) * 576 + (i0 + ii) * 24;
        if (lane < 24) {
            #pragma unroll
            for (int p = 0; p < 9; ++p)
                ob[p * 576 + lane] = S[(lane + p) * 25 + lane] * sc;
        }
        __syncwarp();
    }
}

extern "C" void kernel_launch(void* const* d_in, const int* in_sizes, int n_in,
                              void* d_out, int out_size)
{
    const float* x1 = (const float*)d_in[0];
    const float* x2 = (const float*)d_in[1];
    float* out = (float*)d_out;

    cudaFuncSetAttribute(mma_kernel,
                         cudaFuncAttributeMaxDynamicSharedMemorySize, SMEM_BYTES);

    dim3 pgrid(24, 32);
    prep_kernel<<<pgrid, 256>>>(x1, x2);              // launch 0
    dim3 mgrid(12, BB);
    mma_kernel<<<mgrid, NT, SMEM_BYTES>>>(out);       // launch 1 -> idx 3 profiled
}

// round 15
// speedup vs baseline: 3.3397x; 1.5412x over previous
#include <cuda_runtime.h>
#include <cstdint>

// ================= problem constants =================
#define BB 16
#define CC 256
#define NT 288                       // 9 warps = 9 q-displacements
#define SROW1 264                    // x1 smem row stride (floats), ≡8 mod 32
#define X1ROWS 24                    // 1 i-row x 24 j
#define SMEM_BYTES 28800             // max(tile 24*264*4=25344, epi 9*800*4=28800)

// A: K-major, channel pair-permuted within 8: g_At[b][i*24+j][k']
__device__ __align__(16) float g_At[(size_t)BB * 576 * CC];
// B: fragment-major [b][y'(32)][kc(32)][mt(2)][lane(32)][4]; .bss zeros = padding
__device__ __align__(16) float g_B2[(size_t)BB * 32 * 32 * 2 * 128];

__device__ __forceinline__ float tf32r(float x) {
    uint32_t u;
    asm("cvt.rna.tf32.f32 %0, %1;" : "=r"(u) : "f"(x));
    return __uint_as_float(u);
}
__device__ __forceinline__ uint32_t smem_u32(const void* p) {
    uint32_t a;
    asm("{ .reg .u64 t; cvta.to.shared.u64 t, %1; cvt.u32.u64 %0, t; }"
        : "=r"(a) : "l"(p));
    return a;
}
__device__ __forceinline__ void cp16(uint32_t s, const float* g) {
    asm volatile("cp.async.cg.shared.global [%0], [%1], 16;" :: "r"(s), "l"(g));
}
__device__ __forceinline__ void mma_tf32(float* d, const uint32_t* a,
                                         const uint32_t* b) {
    asm volatile(
        "mma.sync.aligned.m16n8k8.row.col.f32.tf32.tf32.f32 "
        "{%0,%1,%2,%3}, {%4,%5,%6,%7}, {%8,%9}, {%0,%1,%2,%3};"
        : "+f"(d[0]), "+f"(d[1]), "+f"(d[2]), "+f"(d[3])
        : "r"(a[0]), "r"(a[1]), "r"(a[2]), "r"(a[3]), "r"(b[0]), "r"(b[1]));
}

// ===== prep: even-grid compact + tf32; A->pair-permuted K-major, B->fragment-major =====
__global__ void prep_kernel(const float* __restrict__ x1,
                            const float* __restrict__ x2)
{
    __shared__ float tile[32][25];
    const int row = blockIdx.x;          // 0..23 : i (A) or y (B)
    const int b   = blockIdx.y >> 1;
    const bool isB = blockIdx.y & 1;
    const float* src = isB ? x2 : x1;
    const int t = threadIdx.x;

    #pragma unroll 1
    for (int cb = 0; cb < 8; ++cb) {
        const int c0 = cb * 32;
        {
            const int c  = t >> 3;
            const int j0 = (t & 7) * 3;
            const float* srow = src + ((size_t)(b * CC + c0 + c) * 48 + 2 * row) * 48;
            #pragma unroll
            for (int e = 0; e < 3; ++e)
                tile[c][j0 + e] = tf32r(srow[2 * (j0 + e)]);
        }
        __syncthreads();
        if (!isB) {
            const int c = t & 31, jb = t >> 5;
            const int c8 = c & 7;
            const int cp = (c & ~7) + ((c8 < 4) ? 2 * c8 : 2 * (c8 - 4) + 1);
            #pragma unroll
            for (int e = 0; e < 3; ++e) {
                int j = jb + 8 * e;
                g_At[((size_t)(b * 576 + row * 24 + j)) * CC + c0 + cp] = tile[c][j];
            }
        } else {
            // 1024 floats: [kcl(4)][mt(2)][lane(32)][el(4)]
            #pragma unroll
            for (int e = 0; e < 4; ++e) {
                int lin = t + 256 * e;           // 0..1023
                int kcl  = lin >> 8;
                int rem  = lin & 255;            // [mt][lane][el]
                int mt   = rem >> 7;
                int rem2 = rem & 127;
                int lane = rem2 >> 2, el = rem2 & 3;
                int gg = lane >> 2, tt4 = lane & 3;
                int xp = mt * 16 + gg + 8 * (el & 1);      // x' 0..31
                int c  = kcl * 8 + tt4 + 4 * (el >> 1);    // k within 32
                float v = (xp >= 4 && xp < 28) ? tile[c][xp - 4] : 0.f;
                size_t idx = (((size_t)(b * 32 + row + 4) * 32 + cb * 4 + kcl) * 2 + mt)
                             * 128 + rem2;
                g_B2[idx] = v;
            }
        }
        __syncthreads();
    }
}

// ===== barrier-free banded TF32 warp-MMA; 1 i-row per CTA, 3 CTAs/SM =====
__global__ __launch_bounds__(NT, 3)
void mma_kernel(float* __restrict__ out)
{
    extern __shared__ float sm[];
    const uint32_t smb = smem_u32(sm);
    const int tid = threadIdx.x;
    const int q = tid >> 5, lane = tid & 31;
    const int g = lane >> 2, t4 = lane & 3;
    const int i0 = blockIdx.x;           // 0..23
    const int b  = blockIdx.y;

    // ---- one-shot x1 tile load: 24 rows x 256 k' (pair-permuted) ----
    {
        const float* Ab = g_At + (size_t)(b * 576 + i0 * 24) * CC;
        for (int e = tid; e < X1ROWS * 64; e += NT) {
            int r = e >> 6, s = e & 63;
            cp16(smb + (uint32_t)(r * (SROW1 * 4) + s * 16), Ab + r * CC + s * 4);
        }
        asm volatile("cp.async.commit_group;" ::: "memory");
        asm volatile("cp.async.wait_group 0;" ::: "memory");
    }
    __syncthreads();                     // the ONLY block barrier before epilogue

    // x2 fragments: one LDG.128 per (kc, mt)
    const float4* __restrict__ Bq = (const float4*)
        (g_B2 + (size_t)(b * 32 + i0 + q) * 8192) + lane;

    float acc[2][3][4];
    #pragma unroll
    for (int mt = 0; mt < 2; ++mt)
        #pragma unroll
        for (int nt = 0; nt < 3; ++nt)
            #pragma unroll
            for (int e = 0; e < 4; ++e) acc[mt][nt][e] = 0.f;

    #pragma unroll 4
    for (int kc = 0; kc < 32; ++kc) {
        uint32_t af[2][4], bf[3][2];
        #pragma unroll
        for (int mt = 0; mt < 2; ++mt) {
            float4 v = Bq[kc * 64 + mt * 32];
            af[mt][0] = __float_as_uint(v.x);   // (k,      x')
            af[mt][1] = __float_as_uint(v.y);   // (k,      x'+8)
            af[mt][2] = __float_as_uint(v.z);   // (k+4,    x')
            af[mt][3] = __float_as_uint(v.w);   // (k+4,    x'+8)
        }
        #pragma unroll
        for (int nt = 0; nt < 3; ++nt) {
            float2 bp = *(const float2*)(sm + (nt * 8 + g) * SROW1 + kc * 8 + 2 * t4);
            bf[nt][0] = __float_as_uint(bp.x);  // k = kc*8+t4
            bf[nt][1] = __float_as_uint(bp.y);  // k = kc*8+t4+4
        }
        #pragma unroll
        for (int mt = 0; mt < 2; ++mt)
            #pragma unroll
            for (int nt = 0; nt < 3; ++nt)
                mma_tf32(acc[mt][nt], af[mt], bf[nt]);
    }
    __syncthreads();                     // warps done with x1s; reuse as scratch

    // epilogue: warp q scratch 32x25
    float* S = sm + q * 800;
    const float sc = 1.0f / 256.0f;
    #pragma unroll
    for (int mt = 0; mt < 2; ++mt)
        #pragma unroll
        for (int nt = 0; nt < 3; ++nt) {
            float* s0 = S + (mt * 16 + g) * 25 + nt * 8 + 2 * t4;
            s0[0]          = acc[mt][nt][0];
            s0[1]          = acc[mt][nt][1];
            s0[8 * 25]     = acc[mt][nt][2];
            s0[8 * 25 + 1] = acc[mt][nt][3];
        }
    __syncwarp();
    float* ob = out + ((size_t)b * 81 + q * 9) * 576 + i0 * 24;
    if (lane < 24) {
        #pragma unroll
        for (int p = 0; p < 9; ++p)
            ob[p * 576 + lane] = S[(lane + p) * 25 + lane] * sc;
    }
}

extern "C" void kernel_launch(void* const* d_in, const int* in_sizes, int n_in,
                              void* d_out, int out_size)
{
    const float* x1 = (const float*)d_in[0];
    const float* x2 = (const float*)d_in[1];
    float* out = (float*)d_out;

    cudaFuncSetAttribute(mma_kernel,
                         cudaFuncAttributeMaxDynamicSharedMemorySize, SMEM_BYTES);

    dim3 pgrid(24, 32);
    prep_kernel<<<pgrid, 256>>>(x1, x2);              // launch 0
    dim3 mgrid(24, BB);
    mma_kernel<<<mgrid, NT, SMEM_BYTES>>>(out);       // launch 1 -> idx 3 profiled
}